// round 6
// baseline (speedup 1.0000x reference)
#include <cuda_runtime.h>

#define HH 512
#define WW 512
#define NC 48
#define NP (HH*WW)
#define NQ 12
#define CPT 6    // channels per thread
#define GPP 8    // channel-groups (warps) per pixel strip
#define PXW 64   // pixels per block (32 lanes x 2 px/thread)

// ---- scratch (static device globals: allocation-free, graph-safe) ----
__device__ float g_a[NC*NP];
__device__ float g_b[NC*NP];
__device__ float g_s0[NP];
__device__ float g_s1[NP];
__device__ float g_aux[12*NP];   // 12 planar scalar coeff planes

// ---- K0: per-pixel stencil weights (periodic rolls on Dt), folded /dg, 0.5*hinv,
//          zero-pad masks; scalar planar output ----
__global__ void k_aux(const float* __restrict__ Dt, const float* __restrict__ dg,
                      const float* __restrict__ hinv) {
    int p = blockIdx.x * blockDim.x + threadIdx.x;
    if (p >= NP) return;
    int h = p >> 9, w = p & 511;
    int hm = (h - 1) & 511, hp = (h + 1) & 511;
    int wm = (w - 1) & 511, wp = (w + 1) & 511;
    #define DTA(hh,ww) Dt[(((hh)<<9)+(ww))*3+0]
    #define DTC(hh,ww) Dt[(((hh)<<9)+(ww))*3+1]
    #define DTB(hh,ww) Dt[(((hh)<<9)+(ww))*3+2]
    float a00 = DTA(h,w),  c00 = DTC(h,w),  b00 = DTB(h,w);
    float a_hm = DTA(hm,w), b_hm = DTB(hm,w);
    float a_hp = DTA(hp,w), b_hp = DTB(hp,w);
    float c_wm = DTC(h,wm), b_wm = DTB(h,wm);
    float c_wp = DTC(h,wp), b_wp = DTB(h,wp);
    float b_mm = DTB(hm,wm);
    float b_mp = DTB(hm,wp);
    float b_pm = DTB(hp,wm);
    float b_pp = DTB(hp,wp);
    #undef DTA
    #undef DTC
    #undef DTB
    float A0 = (fabsf(b_pm) - b_pm + fabsf(b00) - b00) * 0.25f;
    float A1 = (c_wm + c00 - fabsf(b_wm) - fabsf(b00)) * 0.5f;
    float A2 = (fabsf(b_mm) + b_mm + fabsf(b00) + b00) * 0.25f;
    float A3 = (a_hp + a00 - fabsf(b_hp) - fabsf(b00)) * 0.5f;
    float A4 = -(a_hp + 2.0f*a00 + a_hm) * 0.5f
               - (fabsf(b_pm) - b_pm + fabsf(b_mm) + b_mm) * 0.25f
               - (fabsf(b_pp) + b_pp + fabsf(b_mp) - b_mp) * 0.25f
               + (fabsf(b_hp) + fabsf(b_hm) + fabsf(b_wp) + fabsf(b_wm) + 2.0f*fabsf(b00)) * 0.5f
               - (c_wp + 2.0f*c00 + c_wm) * 0.5f;
    float A5 = (a_hm + a00 - fabsf(b_hm) - fabsf(b00)) * 0.5f;
    float A6 = (fabsf(b_pp) + b_pp + fabsf(b00) + b00) * 0.25f;
    float A7 = (c_wp + c00 - fabsf(b_wp) - fabsf(b00)) * 0.5f;
    float A8 = (fabsf(b_mp) - b_mp + fabsf(b00) - b00) * 0.25f;

    float inv_dg = 1.0f / dg[p];
    float mhm = (h > 0)      ? 1.0f : 0.0f;
    float mhp = (h < HH - 1) ? 1.0f : 0.0f;
    float mwm = (w > 0)      ? 1.0f : 0.0f;
    float mwp = (w < WW - 1) ? 1.0f : 0.0f;

    g_aux[0*NP+p]  = A0 * inv_dg * mhm * mwm;
    g_aux[1*NP+p]  = A1 * inv_dg * mhm;
    g_aux[2*NP+p]  = A2 * inv_dg * mhm * mwp;
    g_aux[3*NP+p]  = A3 * inv_dg * mwm;
    g_aux[4*NP+p]  = A4 * inv_dg;
    g_aux[5*NP+p]  = A5 * inv_dg * mwp;
    g_aux[6*NP+p]  = A6 * inv_dg * mhp * mwm;
    g_aux[7*NP+p]  = A7 * inv_dg * mhp;
    g_aux[8*NP+p]  = A8 * inv_dg * mhp * mwp;
    g_aux[9*NP+p]  = 0.5f * hinv[p*3+0];
    g_aux[10*NP+p] = 0.5f * hinv[p*3+1];
    g_aux[11*NP+p] =        hinv[p*3+2];
}

// ---- K1: transpose interleaved v -> planar g_a, compute s0 = logsumexp ----
__global__ void __launch_bounds__(256) k_in(const float* __restrict__ v) {
    int p = blockIdx.x * blockDim.x + threadIdx.x;
    if (p >= NP) return;
    const float4* xp = (const float4*)v + (size_t)p * NQ;
    float4 t[NQ];
    float m = -3.402823466e38f;
    #pragma unroll
    for (int q = 0; q < NQ; q++) {
        t[q] = xp[q];
        m = fmaxf(m, fmaxf(fmaxf(t[q].x, t[q].y), fmaxf(t[q].z, t[q].w)));
    }
    float sum = 0.0f;
    #pragma unroll
    for (int q = 0; q < NQ; q++) {
        sum += __expf(t[q].x - m) + __expf(t[q].y - m)
             + __expf(t[q].z - m) + __expf(t[q].w - m);
        g_a[(q*4+0)*NP + p] = t[q].x;
        g_a[(q*4+1)*NP + p] = t[q].y;
        g_a[(q*4+2)*NP + p] = t[q].z;
        g_a[(q*4+3)*NP + p] = t[q].w;
    }
    g_s0[p] = m + __logf(sum);
}

// ---- K2: fused Euler step; each thread = 2 horiz pixels x 6 channels. ----
__global__ void __launch_bounds__(32*GPP, 3) k_step(int ssel, int last,
                                                    float* __restrict__ out_ilv) {
    __shared__ float2 red0[GPP][32];
    __shared__ float2 red1[GPP][32];
    __shared__ float2 red2[GPP][32];

    int tx = threadIdx.x;           // lane: pixel pair within 64-px strip
    int ty = threadIdx.y;           // channel group
    int c0 = ty * CPT;

    int h  = blockIdx.x >> 3;            // 8 blocks per row (512/64)
    int w  = ((blockIdx.x & 7) << 6) + 2 * tx;   // even
    int hm = (h - 1) & 511, hp = (h + 1) & 511;
    int b0 = h << 9, bm = hm << 9, bp = hp << 9;
    int wm1 = (w - 1) & 511;
    int wp2 = (w + 2) & 511;
    int pA = b0 + w;                     // pixel A; pixel B = pA+1

    const float* x  = (ssel == 1) ? (const float*)g_a : (const float*)g_b;
    float* xo       = (ssel == 1) ? g_b : g_a;
    const float* si = (ssel == 1) ? (const float*)g_s0 : (const float*)g_s1;
    float* so       = (ssel == 1) ? g_s1 : g_s0;

    // coefficient pairs: C[k].x = coeff k of pixel A, .y = pixel B
    float2 C[12];
    #pragma unroll
    for (int k = 0; k < 12; k++)
        C[k] = *(const float2*)&g_aux[k*NP + pA];

    float2 s2  = *(const float2*)&si[pA];        // s[w], s[w+1]
    float2 sp2 = *(const float2*)&si[bp + w];    // s at row h+1
    float2 sr2 = *(const float2*)&si[b0 + wp2];  // s[w+2], s[w+3]
    float dsxA = sp2.x - s2.x, dsxB = sp2.y - s2.y;
    float dsyA = s2.y  - s2.x, dsyB = sr2.x - s2.y;

    float2 val[CPT];
    float2 cen[CPT];
    float vsumA = 0.0f, vsumB = 0.0f;
    #pragma unroll
    for (int c = 0; c < CPT; c++) {
        const float* xc = x + (size_t)(c0 + c) * NP;
        float  Lm = xc[bm + wm1], Rm = xc[bm + wp2];
        float2 Mm = *(const float2*)&xc[bm + w];
        float  L0 = xc[b0 + wm1], R0 = xc[b0 + wp2];
        float2 M0 = *(const float2*)&xc[b0 + w];
        float  Lp = xc[bp + wm1], Rp = xc[bp + wp2];
        float2 Mp = *(const float2*)&xc[bp + w];

        // pixel A: taps (Lm,Mm.x,Mm.y | L0,M0.x,M0.y | Lp,Mp.x,Mp.y)
        float accA = C[4].x * M0.x;
        accA = fmaf(C[0].x, Lm,   accA);
        accA = fmaf(C[1].x, Mm.x, accA);
        accA = fmaf(C[2].x, Mm.y, accA);
        accA = fmaf(C[3].x, L0,   accA);
        accA = fmaf(C[5].x, M0.y, accA);
        accA = fmaf(C[6].x, Lp,   accA);
        accA = fmaf(C[7].x, Mp.x, accA);
        accA = fmaf(C[8].x, Mp.y, accA);
        float vxA = (Mp.x - M0.x) - dsxA;
        float vyA = (M0.y - M0.x) - dsyA;
        accA = fmaf(fmaf(C[11].x, vyA, C[9].x * vxA), vxA, accA);
        accA = fmaf(C[10].x, vyA * vyA, accA);
        accA = fmaf(0.1f, M0.x, accA);

        // pixel B: taps (Mm.x,Mm.y,Rm | M0.x,M0.y,R0 | Mp.x,Mp.y,Rp)
        float accB = C[4].y * M0.y;
        accB = fmaf(C[0].y, Mm.x, accB);
        accB = fmaf(C[1].y, Mm.y, accB);
        accB = fmaf(C[2].y, Rm,   accB);
        accB = fmaf(C[3].y, M0.x, accB);
        accB = fmaf(C[5].y, R0,   accB);
        accB = fmaf(C[6].y, Mp.x, accB);
        accB = fmaf(C[7].y, Mp.y, accB);
        accB = fmaf(C[8].y, Rp,   accB);
        float vxB = (Mp.y - M0.y) - dsxB;
        float vyB = (R0   - M0.y) - dsyB;
        accB = fmaf(fmaf(C[11].y, vyB, C[9].y * vxB), vxB, accB);
        accB = fmaf(C[10].y, vyB * vyB, accB);
        accB = fmaf(0.1f, M0.y, accB);

        val[c].x = accA; val[c].y = accB;
        cen[c] = M0;
        vsumA += accA; vsumB += accB;
    }

    // 8-way mean reduction (per pixel)
    red0[ty][tx].x = vsumA;
    red0[ty][tx].y = vsumB;
    __syncthreads();
    float meanA = 0.0f, meanB = 0.0f;
    #pragma unroll
    for (int g = 0; g < GPP; g++) {
        meanA += red0[g][tx].x;
        meanB += red0[g][tx].y;
    }
    meanA *= (1.0f / 48.0f);
    meanB *= (1.0f / 48.0f);

    // Euler update
    #pragma unroll
    for (int c = 0; c < CPT; c++) {
        float tA = val[c].x - meanA;
        float tB = val[c].y - meanB;
        tA = fminf(fmaxf(tA, -1e8f), 1e8f);
        tB = fminf(fmaxf(tB, -1e8f), 1e8f);
        val[c].x = fmaf(0.2f, tA, cen[c].x);
        val[c].y = fmaf(0.2f, tB, cen[c].y);
    }

    if (!last) {
        float mA = val[0].x, mB = val[0].y;
        #pragma unroll
        for (int c = 1; c < CPT; c++) {
            mA = fmaxf(mA, val[c].x);
            mB = fmaxf(mB, val[c].y);
        }
        red1[ty][tx].x = mA;
        red1[ty][tx].y = mB;
        #pragma unroll
        for (int c = 0; c < CPT; c++)
            *(float2*)&xo[(size_t)(c0 + c) * NP + pA] = val[c];
        __syncthreads();
        mA = red1[0][tx].x; mB = red1[0][tx].y;
        #pragma unroll
        for (int g = 1; g < GPP; g++) {
            mA = fmaxf(mA, red1[g][tx].x);
            mB = fmaxf(mB, red1[g][tx].y);
        }
        float esA = 0.0f, esB = 0.0f;
        #pragma unroll
        for (int c = 0; c < CPT; c++) {
            esA += __expf(val[c].x - mA);
            esB += __expf(val[c].y - mB);
        }
        red2[ty][tx].x = esA;
        red2[ty][tx].y = esB;
        __syncthreads();
        if (ty == 0) {
            float sumA = 0.0f, sumB = 0.0f;
            #pragma unroll
            for (int g = 0; g < GPP; g++) {
                sumA += red2[g][tx].x;
                sumB += red2[g][tx].y;
            }
            float2 os;
            os.x = mA + __logf(sumA);
            os.y = mB + __logf(sumB);
            *(float2*)&so[pA] = os;
        }
    } else {
        // interleaved output: 6 contiguous floats per pixel at out[p*48 + c0]
        float2* oA = (float2*)(out_ilv + (size_t)pA * NC + c0);
        float2* oB = (float2*)(out_ilv + (size_t)(pA + 1) * NC + c0);
        #pragma unroll
        for (int q = 0; q < 3; q++) {
            float2 a, b;
            a.x = val[q*2+0].x; a.y = val[q*2+1].x;
            b.x = val[q*2+0].y; b.y = val[q*2+1].y;
            oA[q] = a;
            oB[q] = b;
        }
    }
}

extern "C" void kernel_launch(void* const* d_in, const int* in_sizes, int n_in,
                              void* d_out, int out_size) {
    const float* v    = (const float*)d_in[0];
    const float* Dt   = (const float*)d_in[1];
    const float* dg   = (const float*)d_in[2];
    const float* hinv = (const float*)d_in[3];
    float* out = (float*)d_out;

    k_aux<<<NP / 256, 256>>>(Dt, dg, hinv);
    k_in<<<NP / 256, 256>>>(v);

    dim3 blk(32, GPP);
    int grid = NP / PXW;   // 4096
    k_step<<<grid, blk>>>(1, 0, out);
    k_step<<<grid, blk>>>(2, 0, out);
    k_step<<<grid, blk>>>(1, 0, out);
    k_step<<<grid, blk>>>(2, 0, out);
    k_step<<<grid, blk>>>(1, 1, out);
}

// round 7
// speedup vs baseline: 1.0106x; 1.0106x over previous
#include <cuda_runtime.h>

#define HH 512
#define WW 512
#define NC 48
#define NP (HH*WW)
#define NQ 12
#define CPT 6    // channels per thread
#define GPP 8    // channel-groups (warps) per pixel strip
#define PXW 64   // pixels per block (32 lanes x 2 px/thread)

// ---- scratch (static device globals: allocation-free, graph-safe) ----
__device__ float g_a[NC*NP];
__device__ float g_b[NC*NP];
__device__ float g_s0[NP];
__device__ float g_s1[NP];
__device__ float g_aux[12*NP];   // 12 planar scalar coeff planes

// ---- K0: fused init: stencil weights from Dt (+fold /dg, 0.5*hinv, pad masks)
//          AND transpose v -> planar g_a AND s0 = logsumexp(v) ----
__global__ void __launch_bounds__(256) k_init(const float* __restrict__ v,
                                              const float* __restrict__ Dt,
                                              const float* __restrict__ dg,
                                              const float* __restrict__ hinv) {
    int p = blockIdx.x * blockDim.x + threadIdx.x;
    if (p >= NP) return;
    int h = p >> 9, w = p & 511;
    int hm = (h - 1) & 511, hp = (h + 1) & 511;
    int wm = (w - 1) & 511, wp = (w + 1) & 511;
    #define DTA(hh,ww) Dt[(((hh)<<9)+(ww))*3+0]
    #define DTC(hh,ww) Dt[(((hh)<<9)+(ww))*3+1]
    #define DTB(hh,ww) Dt[(((hh)<<9)+(ww))*3+2]
    float a00 = DTA(h,w),  c00 = DTC(h,w),  b00 = DTB(h,w);
    float a_hm = DTA(hm,w), b_hm = DTB(hm,w);
    float a_hp = DTA(hp,w), b_hp = DTB(hp,w);
    float c_wm = DTC(h,wm), b_wm = DTB(h,wm);
    float c_wp = DTC(h,wp), b_wp = DTB(h,wp);
    float b_mm = DTB(hm,wm);
    float b_mp = DTB(hm,wp);
    float b_pm = DTB(hp,wm);
    float b_pp = DTB(hp,wp);
    #undef DTA
    #undef DTC
    #undef DTB
    float A0 = (fabsf(b_pm) - b_pm + fabsf(b00) - b00) * 0.25f;
    float A1 = (c_wm + c00 - fabsf(b_wm) - fabsf(b00)) * 0.5f;
    float A2 = (fabsf(b_mm) + b_mm + fabsf(b00) + b00) * 0.25f;
    float A3 = (a_hp + a00 - fabsf(b_hp) - fabsf(b00)) * 0.5f;
    float A4 = -(a_hp + 2.0f*a00 + a_hm) * 0.5f
               - (fabsf(b_pm) - b_pm + fabsf(b_mm) + b_mm) * 0.25f
               - (fabsf(b_pp) + b_pp + fabsf(b_mp) - b_mp) * 0.25f
               + (fabsf(b_hp) + fabsf(b_hm) + fabsf(b_wp) + fabsf(b_wm) + 2.0f*fabsf(b00)) * 0.5f
               - (c_wp + 2.0f*c00 + c_wm) * 0.5f;
    float A5 = (a_hm + a00 - fabsf(b_hm) - fabsf(b00)) * 0.5f;
    float A6 = (fabsf(b_pp) + b_pp + fabsf(b00) + b00) * 0.25f;
    float A7 = (c_wp + c00 - fabsf(b_wp) - fabsf(b00)) * 0.5f;
    float A8 = (fabsf(b_mp) - b_mp + fabsf(b00) - b00) * 0.25f;

    float inv_dg = 1.0f / dg[p];
    float mhm = (h > 0)      ? 1.0f : 0.0f;
    float mhp = (h < HH - 1) ? 1.0f : 0.0f;
    float mwm = (w > 0)      ? 1.0f : 0.0f;
    float mwp = (w < WW - 1) ? 1.0f : 0.0f;

    g_aux[0*NP+p]  = A0 * inv_dg * mhm * mwm;
    g_aux[1*NP+p]  = A1 * inv_dg * mhm;
    g_aux[2*NP+p]  = A2 * inv_dg * mhm * mwp;
    g_aux[3*NP+p]  = A3 * inv_dg * mwm;
    g_aux[4*NP+p]  = A4 * inv_dg;
    g_aux[5*NP+p]  = A5 * inv_dg * mwp;
    g_aux[6*NP+p]  = A6 * inv_dg * mhp * mwm;
    g_aux[7*NP+p]  = A7 * inv_dg * mhp;
    g_aux[8*NP+p]  = A8 * inv_dg * mhp * mwp;
    g_aux[9*NP+p]  = 0.5f * hinv[p*3+0];
    g_aux[10*NP+p] = 0.5f * hinv[p*3+1];
    g_aux[11*NP+p] =        hinv[p*3+2];

    // transpose + logsumexp
    const float4* xp = (const float4*)v + (size_t)p * NQ;
    float4 t[NQ];
    float m = -3.402823466e38f;
    #pragma unroll
    for (int q = 0; q < NQ; q++) {
        t[q] = xp[q];
        m = fmaxf(m, fmaxf(fmaxf(t[q].x, t[q].y), fmaxf(t[q].z, t[q].w)));
    }
    float sum = 0.0f;
    #pragma unroll
    for (int q = 0; q < NQ; q++) {
        sum += __expf(t[q].x - m) + __expf(t[q].y - m)
             + __expf(t[q].z - m) + __expf(t[q].w - m);
        g_a[(q*4+0)*NP + p] = t[q].x;
        g_a[(q*4+1)*NP + p] = t[q].y;
        g_a[(q*4+2)*NP + p] = t[q].z;
        g_a[(q*4+3)*NP + p] = t[q].w;
    }
    g_s0[p] = m + __logf(sum);
}

// ---- K2: fused Euler step; each thread = 2 horiz pixels x 6 channels. ----
__global__ void __launch_bounds__(32*GPP, 4) k_step(int ssel, int last,
                                                    float* __restrict__ out_ilv) {
    __shared__ float2 red0[GPP][32];
    __shared__ float2 red1[GPP][32];
    __shared__ float2 red2[GPP][32];

    int tx = threadIdx.x;           // lane: pixel pair within 64-px strip
    int ty = threadIdx.y;           // channel group
    int c0 = ty * CPT;

    int h  = blockIdx.x >> 3;            // 8 blocks per row (512/64)
    int w  = ((blockIdx.x & 7) << 6) + 2 * tx;   // even
    int hm = (h - 1) & 511, hp = (h + 1) & 511;
    int b0 = h << 9, bm = hm << 9, bp = hp << 9;
    int wm1 = (w - 1) & 511;
    int wp2 = (w + 2) & 511;
    int pA = b0 + w;                     // pixel A; pixel B = pA+1

    const float* x  = (ssel == 1) ? (const float*)g_a : (const float*)g_b;
    float* xo       = (ssel == 1) ? g_b : g_a;
    const float* si = (ssel == 1) ? (const float*)g_s0 : (const float*)g_s1;
    float* so       = (ssel == 1) ? g_s1 : g_s0;

    // coefficient pairs: C[k].x = coeff k of pixel A, .y = pixel B
    float2 C[12];
    #pragma unroll
    for (int k = 0; k < 12; k++)
        C[k] = *(const float2*)&g_aux[k*NP + pA];

    float2 s2  = *(const float2*)&si[pA];        // s[w], s[w+1]
    float2 sp2 = *(const float2*)&si[bp + w];    // s at row h+1
    float2 sr2 = *(const float2*)&si[b0 + wp2];  // s[w+2], s[w+3]
    float dsxA = sp2.x - s2.x, dsxB = sp2.y - s2.y;
    float dsyA = s2.y  - s2.x, dsyB = sr2.x - s2.y;

    float2 val[CPT];
    float vsumA = 0.0f, vsumB = 0.0f;
    #pragma unroll
    for (int c = 0; c < CPT; c++) {
        const float* xc = x + (size_t)(c0 + c) * NP;
        float  Lm = xc[bm + wm1], Rm = xc[bm + wp2];
        float2 Mm = *(const float2*)&xc[bm + w];
        float  L0 = xc[b0 + wm1], R0 = xc[b0 + wp2];
        float2 M0 = *(const float2*)&xc[b0 + w];
        float  Lp = xc[bp + wm1], Rp = xc[bp + wp2];
        float2 Mp = *(const float2*)&xc[bp + w];

        // pixel A
        float accA = C[4].x * M0.x;
        accA = fmaf(C[0].x, Lm,   accA);
        accA = fmaf(C[1].x, Mm.x, accA);
        accA = fmaf(C[2].x, Mm.y, accA);
        accA = fmaf(C[3].x, L0,   accA);
        accA = fmaf(C[5].x, M0.y, accA);
        accA = fmaf(C[6].x, Lp,   accA);
        accA = fmaf(C[7].x, Mp.x, accA);
        accA = fmaf(C[8].x, Mp.y, accA);
        float vxA = (Mp.x - M0.x) - dsxA;
        float vyA = (M0.y - M0.x) - dsyA;
        accA = fmaf(fmaf(C[11].x, vyA, C[9].x * vxA), vxA, accA);
        accA = fmaf(C[10].x, vyA * vyA, accA);
        accA = fmaf(0.1f, M0.x, accA);

        // pixel B
        float accB = C[4].y * M0.y;
        accB = fmaf(C[0].y, Mm.x, accB);
        accB = fmaf(C[1].y, Mm.y, accB);
        accB = fmaf(C[2].y, Rm,   accB);
        accB = fmaf(C[3].y, M0.x, accB);
        accB = fmaf(C[5].y, R0,   accB);
        accB = fmaf(C[6].y, Mp.x, accB);
        accB = fmaf(C[7].y, Mp.y, accB);
        accB = fmaf(C[8].y, Rp,   accB);
        float vxB = (Mp.y - M0.y) - dsxB;
        float vyB = (R0   - M0.y) - dsyB;
        accB = fmaf(fmaf(C[11].y, vyB, C[9].y * vxB), vxB, accB);
        accB = fmaf(C[10].y, vyB * vyB, accB);
        accB = fmaf(0.1f, M0.y, accB);

        val[c].x = accA; val[c].y = accB;
        vsumA += accA; vsumB += accB;
    }

    // 8-way mean reduction (per pixel)
    red0[ty][tx].x = vsumA;
    red0[ty][tx].y = vsumB;
    __syncthreads();
    float meanA = 0.0f, meanB = 0.0f;
    #pragma unroll
    for (int g = 0; g < GPP; g++) {
        meanA += red0[g][tx].x;
        meanB += red0[g][tx].y;
    }
    meanA *= (1.0f / 48.0f);
    meanB *= (1.0f / 48.0f);

    // Euler update (center re-loaded: guaranteed L1 hit, saves 12 live regs)
    #pragma unroll
    for (int c = 0; c < CPT; c++) {
        const float* xc = x + (size_t)(c0 + c) * NP;
        float2 M0 = *(const float2*)&xc[b0 + w];
        float tA = val[c].x - meanA;
        float tB = val[c].y - meanB;
        tA = fminf(fmaxf(tA, -1e8f), 1e8f);
        tB = fminf(fmaxf(tB, -1e8f), 1e8f);
        val[c].x = fmaf(0.2f, tA, M0.x);
        val[c].y = fmaf(0.2f, tB, M0.y);
    }

    if (!last) {
        float mA = val[0].x, mB = val[0].y;
        #pragma unroll
        for (int c = 1; c < CPT; c++) {
            mA = fmaxf(mA, val[c].x);
            mB = fmaxf(mB, val[c].y);
        }
        red1[ty][tx].x = mA;
        red1[ty][tx].y = mB;
        #pragma unroll
        for (int c = 0; c < CPT; c++)
            *(float2*)&xo[(size_t)(c0 + c) * NP + pA] = val[c];
        __syncthreads();
        mA = red1[0][tx].x; mB = red1[0][tx].y;
        #pragma unroll
        for (int g = 1; g < GPP; g++) {
            mA = fmaxf(mA, red1[g][tx].x);
            mB = fmaxf(mB, red1[g][tx].y);
        }
        float esA = 0.0f, esB = 0.0f;
        #pragma unroll
        for (int c = 0; c < CPT; c++) {
            esA += __expf(val[c].x - mA);
            esB += __expf(val[c].y - mB);
        }
        red2[ty][tx].x = esA;
        red2[ty][tx].y = esB;
        __syncthreads();
        if (ty == 0) {
            float sumA = 0.0f, sumB = 0.0f;
            #pragma unroll
            for (int g = 0; g < GPP; g++) {
                sumA += red2[g][tx].x;
                sumB += red2[g][tx].y;
            }
            float2 os;
            os.x = mA + __logf(sumA);
            os.y = mB + __logf(sumB);
            *(float2*)&so[pA] = os;
        }
    } else {
        // interleaved output: 6 contiguous floats per pixel at out[p*48 + c0]
        float2* oA = (float2*)(out_ilv + (size_t)pA * NC + c0);
        float2* oB = (float2*)(out_ilv + (size_t)(pA + 1) * NC + c0);
        #pragma unroll
        for (int q = 0; q < 3; q++) {
            float2 a, b;
            a.x = val[q*2+0].x; a.y = val[q*2+1].x;
            b.x = val[q*2+0].y; b.y = val[q*2+1].y;
            oA[q] = a;
            oB[q] = b;
        }
    }
}

extern "C" void kernel_launch(void* const* d_in, const int* in_sizes, int n_in,
                              void* d_out, int out_size) {
    const float* v    = (const float*)d_in[0];
    const float* Dt   = (const float*)d_in[1];
    const float* dg   = (const float*)d_in[2];
    const float* hinv = (const float*)d_in[3];
    float* out = (float*)d_out;

    k_init<<<NP / 256, 256>>>(v, Dt, dg, hinv);

    dim3 blk(32, GPP);
    int grid = NP / PXW;   // 4096
    k_step<<<grid, blk>>>(1, 0, out);
    k_step<<<grid, blk>>>(2, 0, out);
    k_step<<<grid, blk>>>(1, 0, out);
    k_step<<<grid, blk>>>(2, 0, out);
    k_step<<<grid, blk>>>(1, 1, out);
}